// round 10
// baseline (speedup 1.0000x reference)
#include <cuda_runtime.h>
#include <cuda_bf16.h>
#include <cstdint>

#define NH    16
#define DK    64
#define SEQ   2048
#define BATCH 2
#define HID   1024
#define MROWS (BATCH * SEQ)          // 4096
#define OUT_ELEMS 4194304LL          // 2*2048*1024
#define P_ELEMS   134217728LL        // 2*16*2048*2048

// -------- scratch (static __device__ arrays; allocation-free rule) --------
__device__ __nv_bfloat16 g_qh [BATCH * NH * SEQ * DK];   // [b,h,s,d] hi
__device__ __nv_bfloat16 g_ql [BATCH * NH * SEQ * DK];   // [b,h,s,d] lo
__device__ __nv_bfloat16 g_kh [BATCH * NH * SEQ * DK];
__device__ __nv_bfloat16 g_kl [BATCH * NH * SEQ * DK];
__device__ __nv_bfloat16 g_vth[BATCH * NH * DK * SEQ];   // [b,h,d,s] hi
__device__ __nv_bfloat16 g_vtl[BATCH * NH * DK * SEQ];   // [b,h,d,s] lo
__device__ float g_xr [MROWS * HID];                      // merged-head attn out
__device__ float g_pfb[BATCH * NH * SEQ * SEQ];           // fallback p buffer

// ============================ helpers ======================================
__device__ __forceinline__ uint32_t smem_u32(const void* p) {
    uint32_t a;
    asm("{ .reg .u64 t; cvta.to.shared.u64 t, %1; cvt.u32.u64 %0, t; }"
        : "=r"(a) : "l"(p));
    return a;
}
__device__ __forceinline__ void ldmx4(uint32_t a, uint32_t& r0, uint32_t& r1,
                                      uint32_t& r2, uint32_t& r3) {
    asm volatile("ldmatrix.sync.aligned.m8n8.x4.shared.b16 {%0,%1,%2,%3}, [%4];"
                 : "=r"(r0), "=r"(r1), "=r"(r2), "=r"(r3) : "r"(a));
}
__device__ __forceinline__ void mma16816(float* c, const uint32_t* a,
                                         uint32_t b0, uint32_t b1) {
    asm volatile(
        "mma.sync.aligned.m16n8k16.row.col.f32.bf16.bf16.f32 "
        "{%0,%1,%2,%3}, {%4,%5,%6,%7}, {%8,%9}, {%0,%1,%2,%3};"
        : "+f"(c[0]), "+f"(c[1]), "+f"(c[2]), "+f"(c[3])
        : "r"(a[0]), "r"(a[1]), "r"(a[2]), "r"(a[3]), "r"(b0), "r"(b1));
}
__device__ __forceinline__ void splitf4(float4 v, uint2& hp, uint2& lp) {
    uint32_t h0, h1, l0, l1;
    asm("cvt.rn.bf16x2.f32 %0, %1, %2;" : "=r"(h0) : "f"(v.y), "f"(v.x));
    asm("cvt.rn.bf16x2.f32 %0, %1, %2;" : "=r"(h1) : "f"(v.w), "f"(v.z));
    float lx = v.x - __uint_as_float(h0 << 16);
    float ly = v.y - __uint_as_float(h0 & 0xffff0000u);
    float lz = v.z - __uint_as_float(h1 << 16);
    float lw = v.w - __uint_as_float(h1 & 0xffff0000u);
    asm("cvt.rn.bf16x2.f32 %0, %1, %2;" : "=r"(l0) : "f"(ly), "f"(lx));
    asm("cvt.rn.bf16x2.f32 %0, %1, %2;" : "=r"(l1) : "f"(lw), "f"(lz));
    hp.x = h0; hp.y = h1;
    lp.x = l0; lp.y = l1;
}
__device__ __forceinline__ uint32_t cvt_hi(float v0, float v1) {
    uint32_t h;
    asm("cvt.rn.bf16x2.f32 %0, %1, %2;" : "=r"(h) : "f"(v1), "f"(v0));
    return h;
}
__device__ __forceinline__ uint32_t pack_resid(float v0, float v1, uint32_t hi) {
    float r0 = v0 - __uint_as_float(hi << 16);
    float r1 = v1 - __uint_as_float(hi & 0xffff0000u);
    uint32_t lo;
    asm("cvt.rn.bf16x2.f32 %0, %1, %2;" : "=r"(lo) : "f"(r1), "f"(r0));
    return lo;
}
__device__ __forceinline__ void cp16(uint32_t d, const void* s) {
    asm volatile("cp.async.cg.shared.global [%0], [%1], 16;" :: "r"(d), "l"(s));
}
__device__ __forceinline__ void cp_commit() {
    asm volatile("cp.async.commit_group;" ::: "memory");
}
template <int N>
__device__ __forceinline__ void cp_wait() {
    asm volatile("cp.async.wait_group %0;" :: "n"(N) : "memory");
}

// ===========================================================================
// split-bf16 HMMA NT GEMM (projections + output projection)
// MODE 0: C row-major fp32 [M,N] (+bias)
// MODE 1: head-split bf16 hi/lo planes [b,h,s,d]
// MODE 2: head-split transposed bf16 hi/lo planes [b,h,d,s]
// ===========================================================================
template <int BN, int MODE>
__global__ void __launch_bounds__(256, 2) gemm_mma(
    const float* __restrict__ A, const float* __restrict__ B,
    const float* __restrict__ bias, float* __restrict__ C,
    __nv_bfloat16* __restrict__ Hhi, __nv_bfloat16* __restrict__ Hlo,
    int M, int N, int K, float alpha,
    long long sA, long long sB, long long sC)
{
    constexpr int BM = 128, BK = 32;
    constexpr int PITCH = 80;
    constexpr int A_SZ  = BM * PITCH;
    constexpr int B_SZ  = BN * PITCH;
    constexpr int SBH   = 2 * A_SZ;
    constexpr int STAGE = 2 * A_SZ + 2 * B_SZ;
    constexpr int WARPS_N = 4;
    constexpr int WM = 64;
    constexpr int MT = WM / 16;
    constexpr int NT = 4;
    constexpr int AL = 4;
    constexpr int BL = BN / 32;

    extern __shared__ char smem[];
    const uint32_t sbase = smem_u32(smem);
    const int tid  = threadIdx.x;
    const int wid  = tid >> 5, lane = tid & 31;
    const int wm   = (wid / WARPS_N) * WM;
    const int wn   = (wid % WARPS_N) * 32;

    const float* Ab = A + (long long)blockIdx.z * sA + (long long)(blockIdx.y * BM) * K;
    const float* Bb = B + (long long)blockIdx.z * sB + (long long)(blockIdx.x * BN) * K;
    float*       Cb = C + (long long)blockIdx.z * sC;

    const int r0 = tid >> 3;
    const int kq = (tid & 7) * 4;
    const int soff = r0 * PITCH + kq * 2;

    float acc[MT][NT][4];
#pragma unroll
    for (int i = 0; i < MT; i++)
#pragma unroll
        for (int j = 0; j < NT; j++)
#pragma unroll
            for (int q = 0; q < 4; q++) acc[i][j][q] = 0.0f;

    float4 ra[AL], rb[BL];
    const int nch = K / BK;

#pragma unroll
    for (int i = 0; i < AL; i++)
        ra[i] = *(const float4*)(Ab + (long long)(r0 + 32 * i) * K + kq);
#pragma unroll
    for (int i = 0; i < BL; i++)
        rb[i] = *(const float4*)(Bb + (long long)(r0 + 32 * i) * K + kq);
    {
        char* st0 = smem;
#pragma unroll
        for (int i = 0; i < AL; i++) {
            uint2 hp, lp; splitf4(ra[i], hp, lp);
            *(uint2*)(st0 + i * 32 * PITCH + soff)        = hp;
            *(uint2*)(st0 + A_SZ + i * 32 * PITCH + soff) = lp;
        }
#pragma unroll
        for (int i = 0; i < BL; i++) {
            uint2 hp, lp; splitf4(rb[i], hp, lp);
            *(uint2*)(st0 + SBH + i * 32 * PITCH + soff)        = hp;
            *(uint2*)(st0 + SBH + B_SZ + i * 32 * PITCH + soff) = lp;
        }
    }
    __syncthreads();

    const uint32_t lmo = (uint32_t)((lane & 15) * PITCH + (lane >> 4) * 16);

    for (int c = 0; c < nch; c++) {
        if (c + 1 < nch) {
            const int ko = (c + 1) * BK + kq;
#pragma unroll
            for (int i = 0; i < AL; i++)
                ra[i] = *(const float4*)(Ab + (long long)(r0 + 32 * i) * K + ko);
#pragma unroll
            for (int i = 0; i < BL; i++)
                rb[i] = *(const float4*)(Bb + (long long)(r0 + 32 * i) * K + ko);
        }

        const uint32_t st = sbase + (uint32_t)((c & 1) * STAGE);
#pragma unroll
        for (int kk = 0; kk < 2; kk++) {
            uint32_t ah[MT][4], alo[MT][4], bh[2][4], blo[2][4];
#pragma unroll
            for (int mt = 0; mt < MT; mt++) {
                const uint32_t base = st + (wm + mt * 16) * PITCH + kk * 32 + lmo;
                ldmx4(base,        ah[mt][0],  ah[mt][1],  ah[mt][2],  ah[mt][3]);
                ldmx4(base + A_SZ, alo[mt][0], alo[mt][1], alo[mt][2], alo[mt][3]);
            }
#pragma unroll
            for (int np = 0; np < 2; np++) {
                const uint32_t base = st + SBH + (wn + np * 16) * PITCH + kk * 32 + lmo;
                ldmx4(base,        bh[np][0],  bh[np][1],  bh[np][2],  bh[np][3]);
                ldmx4(base + B_SZ, blo[np][0], blo[np][1], blo[np][2], blo[np][3]);
            }
#pragma unroll
            for (int mt = 0; mt < MT; mt++)
#pragma unroll
                for (int nt = 0; nt < NT; nt++) {
                    const int np = nt >> 1, sel = nt & 1;
                    mma16816(acc[mt][nt], ah[mt],  bh[np][sel],  bh[np][sel + 2]);
                    mma16816(acc[mt][nt], ah[mt],  blo[np][sel], blo[np][sel + 2]);
                    mma16816(acc[mt][nt], alo[mt], bh[np][sel],  bh[np][sel + 2]);
                }
        }

        if (c + 1 < nch) {
            char* stn = smem + ((c + 1) & 1) * STAGE;
#pragma unroll
            for (int i = 0; i < AL; i++) {
                uint2 hp, lp; splitf4(ra[i], hp, lp);
                *(uint2*)(stn + i * 32 * PITCH + soff)        = hp;
                *(uint2*)(stn + A_SZ + i * 32 * PITCH + soff) = lp;
            }
#pragma unroll
            for (int i = 0; i < BL; i++) {
                uint2 hp, lp; splitf4(rb[i], hp, lp);
                *(uint2*)(stn + SBH + i * 32 * PITCH + soff)        = hp;
                *(uint2*)(stn + SBH + B_SZ + i * 32 * PITCH + soff) = lp;
            }
        }
        __syncthreads();
    }

    // ---- epilogue ----
    const int bm = blockIdx.y * BM, bn = blockIdx.x * BN;
#pragma unroll
    for (int mt = 0; mt < MT; mt++) {
#pragma unroll
        for (int nt = 0; nt < NT; nt++) {
            const int m0 = bm + wm + mt * 16 + (lane >> 2);
            const int n0 = bn + wn + nt * 8 + (lane & 3) * 2;
            float b0 = 0.f, b1 = 0.f;
            if (bias) { b0 = bias[n0]; b1 = bias[n0 + 1]; }
            const float v00 = alpha * acc[mt][nt][0] + b0;
            const float v01 = alpha * acc[mt][nt][1] + b1;
            const float v10 = alpha * acc[mt][nt][2] + b0;
            const float v11 = alpha * acc[mt][nt][3] + b1;
            if (MODE == 0) {
                *(float2*)(Cb + (long long)m0 * N + n0)       = make_float2(v00, v01);
                *(float2*)(Cb + (long long)(m0 + 8) * N + n0) = make_float2(v10, v11);
            } else if (MODE == 1) {
                const int b = m0 >> 11, h = n0 >> 6, d = n0 & 63;
                const int s1 = m0 & (SEQ - 1);
                const long long i0 = ((long long)(b * NH + h) * SEQ + s1) * DK + d;
                uint32_t h0 = cvt_hi(v00, v01), l0 = pack_resid(v00, v01, h0);
                uint32_t h1 = cvt_hi(v10, v11), l1 = pack_resid(v10, v11, h1);
                *(uint32_t*)(Hhi + i0)          = h0;
                *(uint32_t*)(Hlo + i0)          = l0;
                *(uint32_t*)(Hhi + i0 + 8 * DK) = h1;
                *(uint32_t*)(Hlo + i0 + 8 * DK) = l1;
            } else {  // MODE 2: V^T planes [b,h,d,s]
                const int b = m0 >> 11, h = n0 >> 6, d = n0 & 63;
                const int s1 = m0 & (SEQ - 1);
                const long long i0 = ((long long)(b * NH + h) * DK + d) * SEQ + s1;
                __nv_bfloat16 h00 = __float2bfloat16(v00);
                __nv_bfloat16 h01 = __float2bfloat16(v01);
                __nv_bfloat16 h10 = __float2bfloat16(v10);
                __nv_bfloat16 h11 = __float2bfloat16(v11);
                Hhi[i0]           = h00;
                Hhi[i0 + SEQ]     = h01;
                Hhi[i0 + 8]       = h10;
                Hhi[i0 + SEQ + 8] = h11;
                Hlo[i0]           = __float2bfloat16(v00 - __bfloat162float(h00));
                Hlo[i0 + SEQ]     = __float2bfloat16(v01 - __bfloat162float(h01));
                Hlo[i0 + 8]       = __float2bfloat16(v10 - __bfloat162float(h10));
                Hlo[i0 + SEQ + 8] = __float2bfloat16(v11 - __bfloat162float(h11));
            }
        }
    }
}

// ===========================================================================
// Fused attention, SINGLE sweep + deferred normalization:
//   e = exp(s/8 - 10) written raw to P; rs accumulated; PV uses raw e;
//   epilogue: xacc *= 1/rs (registers), then in-place rescale of the block's
//   own P slice (mostly L2-resident).
// ===========================================================================
#define KP 144
#define VP 272
#define SQH 0
#define SQL 18432
#define SK0 36864
#define SK1 73728
#define SV0 110592
#define SV1 145408
#define ATTN_SMEM 180224

__device__ __forceinline__ void copy_k(uint32_t dst, const __nv_bfloat16* kh,
                                       const __nv_bfloat16* kl, long long base,
                                       int tid) {
#pragma unroll
    for (int i = 0; i < 4; i++) {
        const int g = tid + i * 256;
        const int r = g >> 3, c = g & 7;
        cp16(dst + r * KP + c * 16,         (const char*)(kh + base) + r * 128 + c * 16);
        cp16(dst + 18432 + r * KP + c * 16, (const char*)(kl + base) + r * 128 + c * 16);
    }
}
__device__ __forceinline__ void copy_v(uint32_t dst, const __nv_bfloat16* vh,
                                       const __nv_bfloat16* vl, long long voff,
                                       int t, int tid) {
#pragma unroll
    for (int i = 0; i < 4; i++) {
        const int g = tid + i * 256;
        const int r = g >> 4, c = g & 15;
        cp16(dst + r * VP + c * 16,
             (const char*)(vh + voff + (long long)r * SEQ) + t * 256 + c * 16);
        cp16(dst + 17408 + r * VP + c * 16,
             (const char*)(vl + voff + (long long)r * SEQ) + t * 256 + c * 16);
    }
}

__global__ void __launch_bounds__(256, 1) attn_fused(
    const __nv_bfloat16* __restrict__ Qhp, const __nv_bfloat16* __restrict__ Qlp,
    const __nv_bfloat16* __restrict__ Khp, const __nv_bfloat16* __restrict__ Klp,
    const __nv_bfloat16* __restrict__ Vhp, const __nv_bfloat16* __restrict__ Vlp,
    float* __restrict__ P, float* __restrict__ XR)
{
    extern __shared__ char sm[];
    const uint32_t sb = smem_u32(sm);
    const int tid = threadIdx.x, lane = tid & 31, wid = tid >> 5;
    const int mt = blockIdx.x, z = blockIdx.y;
    const int b = z >> 4, h = z & 15;
    const int bm = mt * 128, wm = wid * 16;

    const long long koff = (long long)z * SEQ * DK;
    const long long voff = (long long)z * DK * SEQ;
    const long long qoff = koff + (long long)bm * DK;

    // group 0: Q tile
#pragma unroll
    for (int i = 0; i < 4; i++) {
        const int g = tid + i * 256;
        const int r = g >> 3, c = g & 7;
        cp16(sb + SQH + r * KP + c * 16, (const char*)(Qhp + qoff) + r * 128 + c * 16);
        cp16(sb + SQL + r * KP + c * 16, (const char*)(Qlp + qoff) + r * 128 + c * 16);
    }
    cp_commit();
    copy_k(sb + SK0, Khp, Klp, koff, tid);
    copy_v(sb + SV0, Vhp, Vlp, voff, 0, tid);
    cp_commit();
    copy_k(sb + SK1, Khp, Klp, koff + 128LL * DK, tid);
    copy_v(sb + SV1, Vhp, Vlp, voff, 1, tid);
    cp_commit();

    const uint32_t lmoK = (uint32_t)((lane & 15) * KP + (lane >> 4) * 16);
    const uint32_t lmoV = (uint32_t)((lane & 15) * VP + (lane >> 4) * 16);

    uint32_t Qfh[4][4], Qfl[4][4];
    float rs0 = 0.f, rs1 = 0.f;

    float xacc[8][4];
#pragma unroll
    for (int i = 0; i < 8; i++)
#pragma unroll
        for (int q = 0; q < 4; q++) xacc[i][q] = 0.f;

    const int r0 = lane >> 2;
    const int cq = (lane & 3) * 2;
    float* pr0 = P + (long long)z * SEQ * SEQ + (long long)(bm + wm + r0) * SEQ;
    float* pr1 = pr0 + 8 * SEQ;

    // ---------------- single sweep: e write + rs + PV ----------------
    for (int t = 0; t < 16; t++) {
        cp_wait<1>();
        __syncthreads();
        if (t == 0) {
#pragma unroll
            for (int kk = 0; kk < 4; kk++) {
                const uint32_t qa = sb + SQH + wm * KP + kk * 32 + lmoK;
                ldmx4(qa,               Qfh[kk][0], Qfh[kk][1], Qfh[kk][2], Qfh[kk][3]);
                ldmx4(qa + (SQL - SQH), Qfl[kk][0], Qfl[kk][1], Qfl[kk][2], Qfl[kk][3]);
            }
        }
        const uint32_t kb = sb + ((t & 1) ? SK1 : SK0);
        const uint32_t vb = sb + ((t & 1) ? SV1 : SV0);
#pragma unroll
        for (int h2 = 0; h2 < 2; h2++) {
            float sc[8][4];
#pragma unroll
            for (int j = 0; j < 8; j++)
#pragma unroll
                for (int q = 0; q < 4; q++) sc[j][q] = 0.f;
#pragma unroll
            for (int kk = 0; kk < 4; kk++)
#pragma unroll
                for (int ng = 0; ng < 4; ng++) {
                    uint32_t KH[4], KL[4];
                    const uint32_t ka = kb + (h2 * 64 + ng * 16) * KP + kk * 32 + lmoK;
                    ldmx4(ka,         KH[0], KH[1], KH[2], KH[3]);
                    ldmx4(ka + 18432, KL[0], KL[1], KL[2], KL[3]);
#pragma unroll
                    for (int s2 = 0; s2 < 2; s2++) {
                        const int j = ng * 2 + s2;
                        mma16816(sc[j], Qfh[kk], KH[s2], KH[s2 + 2]);
                        mma16816(sc[j], Qfh[kk], KL[s2], KL[s2 + 2]);
                        mma16816(sc[j], Qfl[kk], KH[s2], KH[s2 + 2]);
                    }
                }
            uint32_t ph0[8], ph1[8], pl0[8], pl1[8];
            const int colb = t * 128 + h2 * 64 + cq;
#pragma unroll
            for (int j = 0; j < 8; j++) {
                const float p0 = __expf(fmaf(sc[j][0], 0.125f, -10.f));
                const float p1 = __expf(fmaf(sc[j][1], 0.125f, -10.f));
                const float p2 = __expf(fmaf(sc[j][2], 0.125f, -10.f));
                const float p3 = __expf(fmaf(sc[j][3], 0.125f, -10.f));
                rs0 += p0 + p1;
                rs1 += p2 + p3;
                *(float2*)(pr0 + colb + j * 8) = make_float2(p0, p1);
                *(float2*)(pr1 + colb + j * 8) = make_float2(p2, p3);
                ph0[j] = cvt_hi(p0, p1); pl0[j] = pack_resid(p0, p1, ph0[j]);
                ph1[j] = cvt_hi(p2, p3); pl1[j] = pack_resid(p2, p3, ph1[j]);
            }
#pragma unroll
            for (int u = 0; u < 4; u++) {
                const uint32_t ah[4] = {ph0[2 * u], ph1[2 * u], ph0[2 * u + 1], ph1[2 * u + 1]};
                const uint32_t al[4] = {pl0[2 * u], pl1[2 * u], pl0[2 * u + 1], pl1[2 * u + 1]};
#pragma unroll
                for (int ndg = 0; ndg < 4; ndg++) {
                    uint32_t VH[4], VL[4];
                    const uint32_t va = vb + (ndg * 16) * VP + (h2 * 4 + u) * 32 + lmoV;
                    ldmx4(va,         VH[0], VH[1], VH[2], VH[3]);
                    ldmx4(va + 17408, VL[0], VL[1], VL[2], VL[3]);
#pragma unroll
                    for (int s2 = 0; s2 < 2; s2++) {
                        const int nd = ndg * 2 + s2;
                        mma16816(xacc[nd], ah, VH[s2], VH[s2 + 2]);
                        mma16816(xacc[nd], al, VH[s2], VH[s2 + 2]);
                        mma16816(xacc[nd], ah, VL[s2], VL[s2 + 2]);
                    }
                }
            }
        }
        __syncthreads();
        if (t + 2 < 16) {
            copy_k(sb + ((t & 1) ? SK1 : SK0), Khp, Klp,
                   koff + (long long)(t + 2) * 128 * DK, tid);
            copy_v(sb + ((t & 1) ? SV1 : SV0), Vhp, Vlp, voff, t + 2, tid);
        }
        cp_commit();
    }

    // ---- row sums -> inv; normalize xacc in registers ----
    rs0 += __shfl_xor_sync(0xffffffffu, rs0, 1);
    rs0 += __shfl_xor_sync(0xffffffffu, rs0, 2);
    rs1 += __shfl_xor_sync(0xffffffffu, rs1, 1);
    rs1 += __shfl_xor_sync(0xffffffffu, rs1, 2);
    const float inv0 = 1.0f / rs0, inv1 = 1.0f / rs1;

#pragma unroll
    for (int nd = 0; nd < 8; nd++) {
        xacc[nd][0] *= inv0; xacc[nd][1] *= inv0;
        xacc[nd][2] *= inv1; xacc[nd][3] *= inv1;
    }

    // x out (merged-head layout)
    float* xr = XR + (long long)(b * SEQ + bm + wm + r0) * HID + h * DK + cq;
#pragma unroll
    for (int nd = 0; nd < 8; nd++) {
        *(float2*)(xr + nd * 8)             = make_float2(xacc[nd][0], xacc[nd][1]);
        *(float2*)(xr + 8LL * HID + nd * 8) = make_float2(xacc[nd][2], xacc[nd][3]);
    }

    // ---- phase 2: rescale this block's P slice in place ----
    cp_wait<0>();
    __syncthreads();
    float* sinv = (float*)sm;                 // reuse Q smem region (dead)
    if ((lane & 3) == 0) {
        sinv[wm + r0]     = inv0;
        sinv[wm + 8 + r0] = inv1;
    }
    __syncthreads();

    float4* pb = (float4*)(P + (long long)z * SEQ * SEQ + (long long)bm * SEQ);
#pragma unroll 4
    for (int i = tid; i < 128 * (SEQ / 4); i += 256) {
        const int row = i >> 9;               // SEQ/4 = 512 float4 per row
        const float s = sinv[row];
        float4 v = pb[i];
        v.x *= s; v.y *= s; v.z *= s; v.w *= s;
        pb[i] = v;
    }
}

// ---------------------------------------------------------------------------
extern "C" void kernel_launch(void* const* d_in, const int* in_sizes, int n_in,
                              void* d_out, int out_size)
{
    const float* query = (const float*)d_in[0];
    const float* key_i = (const float*)d_in[1];
    const float* value = (const float*)d_in[2];
    const float* Wq = (const float*)d_in[3];
    const float* bq = (const float*)d_in[4];
    const float* Wk = (const float*)d_in[5];
    const float* bk = (const float*)d_in[6];
    const float* Wv = (const float*)d_in[7];
    const float* bv = (const float*)d_in[8];
    const float* Wo = (const float*)d_in[9];
    const float* bo = (const float*)d_in[10];

    float* out = (float*)d_out;

    __nv_bfloat16 *qh, *ql, *kh, *kl, *vth, *vtl;
    float *gxr, *gpfb;
    cudaGetSymbolAddress((void**)&qh,  g_qh);
    cudaGetSymbolAddress((void**)&ql,  g_ql);
    cudaGetSymbolAddress((void**)&kh,  g_kh);
    cudaGetSymbolAddress((void**)&kl,  g_kl);
    cudaGetSymbolAddress((void**)&vth, g_vth);
    cudaGetSymbolAddress((void**)&vtl, g_vtl);
    cudaGetSymbolAddress((void**)&gxr,  g_xr);
    cudaGetSymbolAddress((void**)&gpfb, g_pfb);

    float* p = ((long long)out_size >= OUT_ELEMS + P_ELEMS) ? (out + OUT_ELEMS)
                                                            : gpfb;

    const int SM128 = 2 * (2 * 128 * 80 + 2 * 128 * 80);  // 81920
    cudaFuncSetAttribute(gemm_mma<128, 0>, cudaFuncAttributeMaxDynamicSharedMemorySize, SM128);
    cudaFuncSetAttribute(gemm_mma<128, 1>, cudaFuncAttributeMaxDynamicSharedMemorySize, SM128);
    cudaFuncSetAttribute(gemm_mma<128, 2>, cudaFuncAttributeMaxDynamicSharedMemorySize, SM128);
    cudaFuncSetAttribute(attn_fused, cudaFuncAttributeMaxDynamicSharedMemorySize, ATTN_SMEM);

    const dim3 blk(256);
    const dim3 gproj(HID / 128, MROWS / 128, 1);

    gemm_mma<128, 1><<<gproj, blk, SM128>>>(query, Wq, bq, nullptr, qh, ql,
                                            MROWS, HID, HID, 1.0f, 0, 0, 0);
    gemm_mma<128, 1><<<gproj, blk, SM128>>>(key_i, Wk, bk, nullptr, kh, kl,
                                            MROWS, HID, HID, 1.0f, 0, 0, 0);
    gemm_mma<128, 2><<<gproj, blk, SM128>>>(value, Wv, bv, nullptr, vth, vtl,
                                            MROWS, HID, HID, 1.0f, 0, 0, 0);

    attn_fused<<<dim3(SEQ / 128, BATCH * NH), blk, ATTN_SMEM>>>(
        qh, ql, kh, kl, vth, vtl, p, gxr);

    gemm_mma<128, 0><<<gproj, blk, SM128>>>(gxr, Wo, bo, out, nullptr, nullptr,
                                            MROWS, HID, HID, 1.0f, 0, 0, 0);
}

// round 12
// speedup vs baseline: 1.0425x; 1.0425x over previous
#include <cuda_runtime.h>
#include <cuda_bf16.h>
#include <cstdint>

#define NH    16
#define DK    64
#define SEQ   2048
#define BATCH 2
#define HID   1024
#define MROWS (BATCH * SEQ)          // 4096
#define OUT_ELEMS 4194304LL          // 2*2048*1024
#define P_ELEMS   134217728LL        // 2*16*2048*2048

// -------- scratch (static __device__ arrays; allocation-free rule) --------
__device__ __nv_bfloat16 g_qh [BATCH * NH * SEQ * DK];   // [b,h,s,d] hi
__device__ __nv_bfloat16 g_ql [BATCH * NH * SEQ * DK];   // [b,h,s,d] lo
__device__ __nv_bfloat16 g_kh [BATCH * NH * SEQ * DK];
__device__ __nv_bfloat16 g_kl [BATCH * NH * SEQ * DK];
__device__ __nv_bfloat16 g_vth[BATCH * NH * DK * SEQ];   // [b,h,d,s] hi
__device__ __nv_bfloat16 g_vtl[BATCH * NH * DK * SEQ];   // [b,h,d,s] lo
__device__ float g_xr  [MROWS * HID];                     // merged-head attn out
__device__ float g_rinv[BATCH * NH * SEQ];                // per-row 1/sum
__device__ float g_pfb [BATCH * NH * SEQ * SEQ];          // fallback p buffer

// ============================ helpers ======================================
__device__ __forceinline__ uint32_t smem_u32(const void* p) {
    uint32_t a;
    asm("{ .reg .u64 t; cvta.to.shared.u64 t, %1; cvt.u32.u64 %0, t; }"
        : "=r"(a) : "l"(p));
    return a;
}
__device__ __forceinline__ void ldmx4(uint32_t a, uint32_t& r0, uint32_t& r1,
                                      uint32_t& r2, uint32_t& r3) {
    asm volatile("ldmatrix.sync.aligned.m8n8.x4.shared.b16 {%0,%1,%2,%3}, [%4];"
                 : "=r"(r0), "=r"(r1), "=r"(r2), "=r"(r3) : "r"(a));
}
__device__ __forceinline__ void mma16816(float* c, const uint32_t* a,
                                         uint32_t b0, uint32_t b1) {
    asm volatile(
        "mma.sync.aligned.m16n8k16.row.col.f32.bf16.bf16.f32 "
        "{%0,%1,%2,%3}, {%4,%5,%6,%7}, {%8,%9}, {%0,%1,%2,%3};"
        : "+f"(c[0]), "+f"(c[1]), "+f"(c[2]), "+f"(c[3])
        : "r"(a[0]), "r"(a[1]), "r"(a[2]), "r"(a[3]), "r"(b0), "r"(b1));
}
__device__ __forceinline__ void splitf4(float4 v, uint2& hp, uint2& lp) {
    uint32_t h0, h1, l0, l1;
    asm("cvt.rn.bf16x2.f32 %0, %1, %2;" : "=r"(h0) : "f"(v.y), "f"(v.x));
    asm("cvt.rn.bf16x2.f32 %0, %1, %2;" : "=r"(h1) : "f"(v.w), "f"(v.z));
    float lx = v.x - __uint_as_float(h0 << 16);
    float ly = v.y - __uint_as_float(h0 & 0xffff0000u);
    float lz = v.z - __uint_as_float(h1 << 16);
    float lw = v.w - __uint_as_float(h1 & 0xffff0000u);
    asm("cvt.rn.bf16x2.f32 %0, %1, %2;" : "=r"(l0) : "f"(ly), "f"(lx));
    asm("cvt.rn.bf16x2.f32 %0, %1, %2;" : "=r"(l1) : "f"(lw), "f"(lz));
    hp.x = h0; hp.y = h1;
    lp.x = l0; lp.y = l1;
}
__device__ __forceinline__ uint32_t cvt_hi(float v0, float v1) {
    uint32_t h;
    asm("cvt.rn.bf16x2.f32 %0, %1, %2;" : "=r"(h) : "f"(v1), "f"(v0));
    return h;
}
__device__ __forceinline__ uint32_t pack_resid(float v0, float v1, uint32_t hi) {
    float r0 = v0 - __uint_as_float(hi << 16);
    float r1 = v1 - __uint_as_float(hi & 0xffff0000u);
    uint32_t lo;
    asm("cvt.rn.bf16x2.f32 %0, %1, %2;" : "=r"(lo) : "f"(r1), "f"(r0));
    return lo;
}
__device__ __forceinline__ void cp16(uint32_t d, const void* s) {
    asm volatile("cp.async.cg.shared.global [%0], [%1], 16;" :: "r"(d), "l"(s));
}
__device__ __forceinline__ void cp_commit() {
    asm volatile("cp.async.commit_group;" ::: "memory");
}
template <int N>
__device__ __forceinline__ void cp_wait() {
    asm volatile("cp.async.wait_group %0;" :: "n"(N) : "memory");
}

// ===========================================================================
// split-bf16 HMMA NT GEMM (projections + output projection) — as R8
// ===========================================================================
template <int BN, int MODE>
__global__ void __launch_bounds__(256, 2) gemm_mma(
    const float* __restrict__ A, const float* __restrict__ B,
    const float* __restrict__ bias, float* __restrict__ C,
    __nv_bfloat16* __restrict__ Hhi, __nv_bfloat16* __restrict__ Hlo,
    int M, int N, int K, float alpha,
    long long sA, long long sB, long long sC)
{
    constexpr int BM = 128, BK = 32;
    constexpr int PITCH = 80;
    constexpr int A_SZ  = BM * PITCH;
    constexpr int B_SZ  = BN * PITCH;
    constexpr int SBH   = 2 * A_SZ;
    constexpr int STAGE = 2 * A_SZ + 2 * B_SZ;
    constexpr int WARPS_N = 4;
    constexpr int WM = 64;
    constexpr int MT = WM / 16;
    constexpr int NT = 4;
    constexpr int AL = 4;
    constexpr int BL = BN / 32;

    extern __shared__ char smem[];
    const uint32_t sbase = smem_u32(smem);
    const int tid  = threadIdx.x;
    const int wid  = tid >> 5, lane = tid & 31;
    const int wm   = (wid / WARPS_N) * WM;
    const int wn   = (wid % WARPS_N) * 32;

    const float* Ab = A + (long long)blockIdx.z * sA + (long long)(blockIdx.y * BM) * K;
    const float* Bb = B + (long long)blockIdx.z * sB + (long long)(blockIdx.x * BN) * K;
    float*       Cb = C + (long long)blockIdx.z * sC;

    const int r0 = tid >> 3;
    const int kq = (tid & 7) * 4;
    const int soff = r0 * PITCH + kq * 2;

    float acc[MT][NT][4];
#pragma unroll
    for (int i = 0; i < MT; i++)
#pragma unroll
        for (int j = 0; j < NT; j++)
#pragma unroll
            for (int q = 0; q < 4; q++) acc[i][j][q] = 0.0f;

    float4 ra[AL], rb[BL];
    const int nch = K / BK;

#pragma unroll
    for (int i = 0; i < AL; i++)
        ra[i] = *(const float4*)(Ab + (long long)(r0 + 32 * i) * K + kq);
#pragma unroll
    for (int i = 0; i < BL; i++)
        rb[i] = *(const float4*)(Bb + (long long)(r0 + 32 * i) * K + kq);
    {
        char* st0 = smem;
#pragma unroll
        for (int i = 0; i < AL; i++) {
            uint2 hp, lp; splitf4(ra[i], hp, lp);
            *(uint2*)(st0 + i * 32 * PITCH + soff)        = hp;
            *(uint2*)(st0 + A_SZ + i * 32 * PITCH + soff) = lp;
        }
#pragma unroll
        for (int i = 0; i < BL; i++) {
            uint2 hp, lp; splitf4(rb[i], hp, lp);
            *(uint2*)(st0 + SBH + i * 32 * PITCH + soff)        = hp;
            *(uint2*)(st0 + SBH + B_SZ + i * 32 * PITCH + soff) = lp;
        }
    }
    __syncthreads();

    const uint32_t lmo = (uint32_t)((lane & 15) * PITCH + (lane >> 4) * 16);

    for (int c = 0; c < nch; c++) {
        if (c + 1 < nch) {
            const int ko = (c + 1) * BK + kq;
#pragma unroll
            for (int i = 0; i < AL; i++)
                ra[i] = *(const float4*)(Ab + (long long)(r0 + 32 * i) * K + ko);
#pragma unroll
            for (int i = 0; i < BL; i++)
                rb[i] = *(const float4*)(Bb + (long long)(r0 + 32 * i) * K + ko);
        }

        const uint32_t st = sbase + (uint32_t)((c & 1) * STAGE);
#pragma unroll
        for (int kk = 0; kk < 2; kk++) {
            uint32_t ah[MT][4], alo[MT][4], bh[2][4], blo[2][4];
#pragma unroll
            for (int mt = 0; mt < MT; mt++) {
                const uint32_t base = st + (wm + mt * 16) * PITCH + kk * 32 + lmo;
                ldmx4(base,        ah[mt][0],  ah[mt][1],  ah[mt][2],  ah[mt][3]);
                ldmx4(base + A_SZ, alo[mt][0], alo[mt][1], alo[mt][2], alo[mt][3]);
            }
#pragma unroll
            for (int np = 0; np < 2; np++) {
                const uint32_t base = st + SBH + (wn + np * 16) * PITCH + kk * 32 + lmo;
                ldmx4(base,        bh[np][0],  bh[np][1],  bh[np][2],  bh[np][3]);
                ldmx4(base + B_SZ, blo[np][0], blo[np][1], blo[np][2], blo[np][3]);
            }
#pragma unroll
            for (int mt = 0; mt < MT; mt++)
#pragma unroll
                for (int nt = 0; nt < NT; nt++) {
                    const int np = nt >> 1, sel = nt & 1;
                    mma16816(acc[mt][nt], ah[mt],  bh[np][sel],  bh[np][sel + 2]);
                    mma16816(acc[mt][nt], ah[mt],  blo[np][sel], blo[np][sel + 2]);
                    mma16816(acc[mt][nt], alo[mt], bh[np][sel],  bh[np][sel + 2]);
                }
        }

        if (c + 1 < nch) {
            char* stn = smem + ((c + 1) & 1) * STAGE;
#pragma unroll
            for (int i = 0; i < AL; i++) {
                uint2 hp, lp; splitf4(ra[i], hp, lp);
                *(uint2*)(stn + i * 32 * PITCH + soff)        = hp;
                *(uint2*)(stn + A_SZ + i * 32 * PITCH + soff) = lp;
            }
#pragma unroll
            for (int i = 0; i < BL; i++) {
                uint2 hp, lp; splitf4(rb[i], hp, lp);
                *(uint2*)(stn + SBH + i * 32 * PITCH + soff)        = hp;
                *(uint2*)(stn + SBH + B_SZ + i * 32 * PITCH + soff) = lp;
            }
        }
        __syncthreads();
    }

    // ---- epilogue ----
    const int bm = blockIdx.y * BM, bn = blockIdx.x * BN;
#pragma unroll
    for (int mt = 0; mt < MT; mt++) {
#pragma unroll
        for (int nt = 0; nt < NT; nt++) {
            const int m0 = bm + wm + mt * 16 + (lane >> 2);
            const int n0 = bn + wn + nt * 8 + (lane & 3) * 2;
            float b0 = 0.f, b1 = 0.f;
            if (bias) { b0 = bias[n0]; b1 = bias[n0 + 1]; }
            const float v00 = alpha * acc[mt][nt][0] + b0;
            const float v01 = alpha * acc[mt][nt][1] + b1;
            const float v10 = alpha * acc[mt][nt][2] + b0;
            const float v11 = alpha * acc[mt][nt][3] + b1;
            if (MODE == 0) {
                *(float2*)(Cb + (long long)m0 * N + n0)       = make_float2(v00, v01);
                *(float2*)(Cb + (long long)(m0 + 8) * N + n0) = make_float2(v10, v11);
            } else if (MODE == 1) {
                const int b = m0 >> 11, h = n0 >> 6, d = n0 & 63;
                const int s1 = m0 & (SEQ - 1);
                const long long i0 = ((long long)(b * NH + h) * SEQ + s1) * DK + d;
                uint32_t h0 = cvt_hi(v00, v01), l0 = pack_resid(v00, v01, h0);
                uint32_t h1 = cvt_hi(v10, v11), l1 = pack_resid(v10, v11, h1);
                *(uint32_t*)(Hhi + i0)          = h0;
                *(uint32_t*)(Hlo + i0)          = l0;
                *(uint32_t*)(Hhi + i0 + 8 * DK) = h1;
                *(uint32_t*)(Hlo + i0 + 8 * DK) = l1;
            } else {  // MODE 2: V^T planes [b,h,d,s]
                const int b = m0 >> 11, h = n0 >> 6, d = n0 & 63;
                const int s1 = m0 & (SEQ - 1);
                const long long i0 = ((long long)(b * NH + h) * DK + d) * SEQ + s1;
                __nv_bfloat16 h00 = __float2bfloat16(v00);
                __nv_bfloat16 h01 = __float2bfloat16(v01);
                __nv_bfloat16 h10 = __float2bfloat16(v10);
                __nv_bfloat16 h11 = __float2bfloat16(v11);
                Hhi[i0]           = h00;
                Hhi[i0 + SEQ]     = h01;
                Hhi[i0 + 8]       = h10;
                Hhi[i0 + SEQ + 8] = h11;
                Hlo[i0]           = __float2bfloat16(v00 - __bfloat162float(h00));
                Hlo[i0 + SEQ]     = __float2bfloat16(v01 - __bfloat162float(h01));
                Hlo[i0 + 8]       = __float2bfloat16(v10 - __bfloat162float(h10));
                Hlo[i0 + SEQ + 8] = __float2bfloat16(v11 - __bfloat162float(h11));
            }
        }
    }
}

// ===========================================================================
// Fused attention, 512 threads: 16 warps; warp-group wg=wid>>3 takes column
// half h2=wg of each K-tile. Single exact sweep writes unnormalized e to P,
// accumulates partial rowsums + partial PV; combined via SMEM at the end.
// Row inverses stored to g_rinv; P rescaled by a separate kernel.
// ===========================================================================
#define KP 144
#define VP 272
#define SQH 0
#define SQL 18432
#define SK0 36864
#define SK1 73728
#define SV0 110592
#define SV1 145408
#define ATTN_SMEM 180224

__device__ __forceinline__ void copy_k(uint32_t dst, const __nv_bfloat16* kh,
                                       const __nv_bfloat16* kl, long long base,
                                       int tid) {
#pragma unroll
    for (int i = 0; i < 2; i++) {
        const int g = tid + i * 512;
        const int r = g >> 3, c = g & 7;
        cp16(dst + r * KP + c * 16,         (const char*)(kh + base) + r * 128 + c * 16);
        cp16(dst + 18432 + r * KP + c * 16, (const char*)(kl + base) + r * 128 + c * 16);
    }
}
__device__ __forceinline__ void copy_v(uint32_t dst, const __nv_bfloat16* vh,
                                       const __nv_bfloat16* vl, long long voff,
                                       int t, int tid) {
#pragma unroll
    for (int i = 0; i < 2; i++) {
        const int g = tid + i * 512;
        const int r = g >> 4, c = g & 15;
        cp16(dst + r * VP + c * 16,
             (const char*)(vh + voff + (long long)r * SEQ) + t * 256 + c * 16);
        cp16(dst + 17408 + r * VP + c * 16,
             (const char*)(vl + voff + (long long)r * SEQ) + t * 256 + c * 16);
    }
}

__global__ void __launch_bounds__(512, 1) attn_fused(
    const __nv_bfloat16* __restrict__ Qhp, const __nv_bfloat16* __restrict__ Qlp,
    const __nv_bfloat16* __restrict__ Khp, const __nv_bfloat16* __restrict__ Klp,
    const __nv_bfloat16* __restrict__ Vhp, const __nv_bfloat16* __restrict__ Vlp,
    float* __restrict__ P, float* __restrict__ XR, float* __restrict__ RINV)
{
    extern __shared__ char sm[];
    const uint32_t sb = smem_u32(sm);
    const int tid = threadIdx.x, lane = tid & 31, wid = tid >> 5;
    const int wi = wid & 7, wg = wid >> 3;      // wg = column half of tile
    const int mt = blockIdx.x, z = blockIdx.y;
    const int b = z >> 4, h = z & 15;
    const int bm = mt * 128, wm = wi * 16;

    const long long koff = (long long)z * SEQ * DK;
    const long long voff = (long long)z * DK * SEQ;
    const long long qoff = koff + (long long)bm * DK;

    // group 0: Q tile
#pragma unroll
    for (int i = 0; i < 2; i++) {
        const int g = tid + i * 512;
        const int r = g >> 3, c = g & 7;
        cp16(sb + SQH + r * KP + c * 16, (const char*)(Qhp + qoff) + r * 128 + c * 16);
        cp16(sb + SQL + r * KP + c * 16, (const char*)(Qlp + qoff) + r * 128 + c * 16);
    }
    cp_commit();
    copy_k(sb + SK0, Khp, Klp, koff, tid);
    copy_v(sb + SV0, Vhp, Vlp, voff, 0, tid);
    cp_commit();
    copy_k(sb + SK1, Khp, Klp, koff + 128LL * DK, tid);
    copy_v(sb + SV1, Vhp, Vlp, voff, 1, tid);
    cp_commit();

    const uint32_t lmoK = (uint32_t)((lane & 15) * KP + (lane >> 4) * 16);
    const uint32_t lmoV = (uint32_t)((lane & 15) * VP + (lane >> 4) * 16);

    uint32_t Qfh[4][4];
    float rs0 = 0.f, rs1 = 0.f;

    float xacc[8][4];
#pragma unroll
    for (int i = 0; i < 8; i++)
#pragma unroll
        for (int q = 0; q < 4; q++) xacc[i][q] = 0.f;

    const int r0 = lane >> 2;
    const int cq = (lane & 3) * 2;
    float* pr0 = P + (long long)z * SEQ * SEQ + (long long)(bm + wm + r0) * SEQ;
    float* pr1 = pr0 + 8 * SEQ;

    // ---------------- single sweep ----------------
    for (int t = 0; t < 16; t++) {
        cp_wait<1>();
        __syncthreads();
        if (t == 0) {
#pragma unroll
            for (int kk = 0; kk < 4; kk++) {
                const uint32_t qa = sb + SQH + wm * KP + kk * 32 + lmoK;
                ldmx4(qa, Qfh[kk][0], Qfh[kk][1], Qfh[kk][2], Qfh[kk][3]);
            }
        }
        const uint32_t kb = sb + ((t & 1) ? SK1 : SK0);
        const uint32_t vb = sb + ((t & 1) ? SV1 : SV0);

        float sc[8][4];
#pragma unroll
        for (int j = 0; j < 8; j++)
#pragma unroll
            for (int q = 0; q < 4; q++) sc[j][q] = 0.f;
#pragma unroll
        for (int kk = 0; kk < 4; kk++) {
            uint32_t Qfl[4];
            {
                const uint32_t qa = sb + SQL + wm * KP + kk * 32 + lmoK;
                ldmx4(qa, Qfl[0], Qfl[1], Qfl[2], Qfl[3]);
            }
#pragma unroll
            for (int ng = 0; ng < 4; ng++) {
                uint32_t KH[4], KL[4];
                const uint32_t ka = kb + (wg * 64 + ng * 16) * KP + kk * 32 + lmoK;
                ldmx4(ka,         KH[0], KH[1], KH[2], KH[3]);
                ldmx4(ka + 18432, KL[0], KL[1], KL[2], KL[3]);
#pragma unroll
                for (int s2 = 0; s2 < 2; s2++) {
                    const int j = ng * 2 + s2;
                    mma16816(sc[j], Qfh[kk], KH[s2], KH[s2 + 2]);
                    mma16816(sc[j], Qfh[kk], KL[s2], KL[s2 + 2]);
                    mma16816(sc[j], Qfl,     KH[s2], KH[s2 + 2]);
                }
            }
        }
        uint32_t ph0[8], ph1[8], pl0[8], pl1[8];
        const int colb = t * 128 + wg * 64 + cq;
#pragma unroll
        for (int j = 0; j < 8; j++) {
            const float p0 = __expf(fmaf(sc[j][0], 0.125f, -10.f));
            const float p1 = __expf(fmaf(sc[j][1], 0.125f, -10.f));
            const float p2 = __expf(fmaf(sc[j][2], 0.125f, -10.f));
            const float p3 = __expf(fmaf(sc[j][3], 0.125f, -10.f));
            rs0 += p0 + p1;
            rs1 += p2 + p3;
            *(float2*)(pr0 + colb + j * 8) = make_float2(p0, p1);
            *(float2*)(pr1 + colb + j * 8) = make_float2(p2, p3);
            ph0[j] = cvt_hi(p0, p1); pl0[j] = pack_resid(p0, p1, ph0[j]);
            ph1[j] = cvt_hi(p2, p3); pl1[j] = pack_resid(p2, p3, ph1[j]);
        }
#pragma unroll
        for (int u = 0; u < 4; u++) {
            const uint32_t ah[4] = {ph0[2 * u], ph1[2 * u], ph0[2 * u + 1], ph1[2 * u + 1]};
            const uint32_t al[4] = {pl0[2 * u], pl1[2 * u], pl0[2 * u + 1], pl1[2 * u + 1]};
#pragma unroll
            for (int ndg = 0; ndg < 4; ndg++) {
                uint32_t VH[4], VL[4];
                const uint32_t va = vb + (ndg * 16) * VP + (wg * 4 + u) * 32 + lmoV;
                ldmx4(va,         VH[0], VH[1], VH[2], VH[3]);
                ldmx4(va + 17408, VL[0], VL[1], VL[2], VL[3]);
#pragma unroll
                for (int s2 = 0; s2 < 2; s2++) {
                    const int nd = ndg * 2 + s2;
                    mma16816(xacc[nd], ah, VH[s2], VH[s2 + 2]);
                    mma16816(xacc[nd], al, VH[s2], VH[s2 + 2]);
                    mma16816(xacc[nd], ah, VL[s2], VL[s2 + 2]);
                }
            }
        }
        __syncthreads();
        if (t + 2 < 16) {
            copy_k(sb + ((t & 1) ? SK1 : SK0), Khp, Klp,
                   koff + (long long)(t + 2) * 128 * DK, tid);
            copy_v(sb + ((t & 1) ? SV1 : SV0), Vhp, Vlp, voff, t + 2, tid);
        }
        cp_commit();
    }

    // ---- combine wg halves, normalize, write XR + row inverses ----
    rs0 += __shfl_xor_sync(0xffffffffu, rs0, 1);
    rs0 += __shfl_xor_sync(0xffffffffu, rs0, 2);
    rs1 += __shfl_xor_sync(0xffffffffu, rs1, 1);
    rs1 += __shfl_xor_sync(0xffffffffu, rs1, 2);

    cp_wait<0>();
    __syncthreads();
    float* xs  = (float*)sm;                   // [128][64] partials from wg1
    float* rsb = (float*)(sm + 32768);         // [128] rowsum partials from wg1

    if (wg == 1) {
        if ((lane & 3) == 0) {
            rsb[wm + r0]     = rs0;
            rsb[wm + 8 + r0] = rs1;
        }
#pragma unroll
        for (int nd = 0; nd < 8; nd++) {
            *(float2*)&xs[(wm + r0) * 64 + nd * 8 + cq]     = make_float2(xacc[nd][0], xacc[nd][1]);
            *(float2*)&xs[(wm + 8 + r0) * 64 + nd * 8 + cq] = make_float2(xacc[nd][2], xacc[nd][3]);
        }
    }
    __syncthreads();

    if (wg == 0) {
        const float inv0 = 1.0f / (rs0 + rsb[wm + r0]);
        const float inv1 = 1.0f / (rs1 + rsb[wm + 8 + r0]);
        if ((lane & 3) == 0) {
            RINV[(long long)z * SEQ + bm + wm + r0]     = inv0;
            RINV[(long long)z * SEQ + bm + wm + 8 + r0] = inv1;
        }
        float* xr = XR + (long long)(b * SEQ + bm + wm + r0) * HID + h * DK + cq;
#pragma unroll
        for (int nd = 0; nd < 8; nd++) {
            const float2 a0 = *(const float2*)&xs[(wm + r0) * 64 + nd * 8 + cq];
            const float2 a1 = *(const float2*)&xs[(wm + 8 + r0) * 64 + nd * 8 + cq];
            *(float2*)(xr + nd * 8) =
                make_float2((xacc[nd][0] + a0.x) * inv0, (xacc[nd][1] + a0.y) * inv0);
            *(float2*)(xr + 8LL * HID + nd * 8) =
                make_float2((xacc[nd][2] + a1.x) * inv1, (xacc[nd][3] + a1.y) * inv1);
        }
    }
}

// ===========================================================================
// P rescale: p[i] *= rinv[row(i)]   (row = i / SEQ)
// ===========================================================================
__global__ void __launch_bounds__(512) rescale_p(float4* __restrict__ P4,
                                                 const float* __restrict__ rinv)
{
    const long long i = (long long)blockIdx.x * 512 + threadIdx.x;  // float4 idx
    const float s = __ldg(rinv + (int)(i >> 9));                    // SEQ/4=512
    float4 v = P4[i];
    v.x *= s; v.y *= s; v.z *= s; v.w *= s;
    P4[i] = v;
}

// ---------------------------------------------------------------------------
extern "C" void kernel_launch(void* const* d_in, const int* in_sizes, int n_in,
                              void* d_out, int out_size)
{
    const float* query = (const float*)d_in[0];
    const float* key_i = (const float*)d_in[1];
    const float* value = (const float*)d_in[2];
    const float* Wq = (const float*)d_in[3];
    const float* bq = (const float*)d_in[4];
    const float* Wk = (const float*)d_in[5];
    const float* bk = (const float*)d_in[6];
    const float* Wv = (const float*)d_in[7];
    const float* bv = (const float*)d_in[8];
    const float* Wo = (const float*)d_in[9];
    const float* bo = (const float*)d_in[10];

    float* out = (float*)d_out;

    __nv_bfloat16 *qh, *ql, *kh, *kl, *vth, *vtl;
    float *gxr, *grinv, *gpfb;
    cudaGetSymbolAddress((void**)&qh,   g_qh);
    cudaGetSymbolAddress((void**)&ql,   g_ql);
    cudaGetSymbolAddress((void**)&kh,   g_kh);
    cudaGetSymbolAddress((void**)&kl,   g_kl);
    cudaGetSymbolAddress((void**)&vth,  g_vth);
    cudaGetSymbolAddress((void**)&vtl,  g_vtl);
    cudaGetSymbolAddress((void**)&gxr,  g_xr);
    cudaGetSymbolAddress((void**)&grinv, g_rinv);
    cudaGetSymbolAddress((void**)&gpfb, g_pfb);

    float* p = ((long long)out_size >= OUT_ELEMS + P_ELEMS) ? (out + OUT_ELEMS)
                                                            : gpfb;

    static cudaStream_t s_aux = nullptr;
    static cudaEvent_t ev_fork = nullptr, ev_join = nullptr;
    if (s_aux == nullptr) {
        cudaStreamCreateWithFlags(&s_aux, cudaStreamNonBlocking);
        cudaEventCreateWithFlags(&ev_fork, cudaEventDisableTiming);
        cudaEventCreateWithFlags(&ev_join, cudaEventDisableTiming);
    }

    const int SM128 = 2 * (2 * 128 * 80 + 2 * 128 * 80);  // 81920
    cudaFuncSetAttribute(gemm_mma<128, 0>, cudaFuncAttributeMaxDynamicSharedMemorySize, SM128);
    cudaFuncSetAttribute(gemm_mma<128, 1>, cudaFuncAttributeMaxDynamicSharedMemorySize, SM128);
    cudaFuncSetAttribute(gemm_mma<128, 2>, cudaFuncAttributeMaxDynamicSharedMemorySize, SM128);
    cudaFuncSetAttribute(attn_fused, cudaFuncAttributeMaxDynamicSharedMemorySize, ATTN_SMEM);

    const dim3 blk(256);
    const dim3 gproj(HID / 128, MROWS / 128, 1);

    gemm_mma<128, 1><<<gproj, blk, SM128>>>(query, Wq, bq, nullptr, qh, ql,
                                            MROWS, HID, HID, 1.0f, 0, 0, 0);
    gemm_mma<128, 1><<<gproj, blk, SM128>>>(key_i, Wk, bk, nullptr, kh, kl,
                                            MROWS, HID, HID, 1.0f, 0, 0, 0);
    gemm_mma<128, 2><<<gproj, blk, SM128>>>(value, Wv, bv, nullptr, vth, vtl,
                                            MROWS, HID, HID, 1.0f, 0, 0, 0);

    attn_fused<<<dim3(SEQ / 128, BATCH * NH), dim3(512), ATTN_SMEM>>>(
        qh, ql, kh, kl, vth, vtl, p, gxr, grinv);

    // fork: rescale P on aux stream, out-projection on main stream (disjoint data)
    cudaEventRecord(ev_fork, 0);
    cudaStreamWaitEvent(s_aux, ev_fork, 0);
    rescale_p<<<(unsigned)(P_ELEMS / 4 / 512), 512, 0, s_aux>>>((float4*)p, grinv);
    cudaEventRecord(ev_join, s_aux);

    gemm_mma<128, 0><<<gproj, blk, SM128>>>(gxr, Wo, bo, out, nullptr, nullptr,
                                            MROWS, HID, HID, 1.0f, 0, 0, 0);
    cudaStreamWaitEvent(0, ev_join, 0);
}